// round 13
// baseline (speedup 1.0000x reference)
#include <cuda_runtime.h>
#include <cstdint>

// Problem constants
#define Bn 32
#define Dn 1024
#define Hn 1024
#define BETA 0.9f

// Output layout (reference return order):
//   [0, B*H)              out   = tanh(a)
//   [B*H, 2*B*H)          u_new = a
//   [2*B*H, +B*D*H)       E_w_new = 0.9*E_w + x[i,d]  (broadcast over h)
//   [..., +B*H)           E_b_new = 0.9*E_b + 1
// a[i,h] = 0.9*u[i,h] + sum_d x[i,d]*w[d,h] + b[h]

#define NB_GEMM 128          // short GEMM blocks
#define NB_EW   760          // stream blocks; total 888 = 2 waves @ 3 blocks/SM
#define NWARPS  (NB_EW * 8)  // 6080 stream warps
#define ROWS    (Bn * Dn)    // 32768 rows of H=1024 floats
#define OFF_UNEW (Bn*Hn)
#define OFF_EW   (2*Bn*Hn)
#define OFF_EB   (2*Bn*Hn + Bn*Dn*Hn)

// ptr-based row ops: p = float4* at (row*256 + lane)
#define LOADP(arr, p)                                                   \
    do { _Pragma("unroll")                                              \
         for (int _k = 0; _k < 8; ++_k) arr[_k] = __ldcs((p) + _k * 32);\
    } while (0)

#define STOREP(arr, p, xv)                                              \
    do { _Pragma("unroll")                                              \
         for (int _k = 0; _k < 8; ++_k) {                               \
             float4 _v;                                                 \
             _v.x = fmaf(BETA, arr[_k].x, xv);                          \
             _v.y = fmaf(BETA, arr[_k].y, xv);                          \
             _v.z = fmaf(BETA, arr[_k].z, xv);                          \
             _v.w = fmaf(BETA, arr[_k].w, xv);                          \
             __stcs((p) + _k * 32, _v);                                 \
         }                                                              \
    } while (0)

__global__ void __launch_bounds__(256, 3)
diag_rtrl_kernel(const float* __restrict__ x,
                 const float* __restrict__ w,
                 const float* __restrict__ b,
                 const float* __restrict__ u,
                 const float* __restrict__ E_w,
                 const float* __restrict__ E_b,
                 float* __restrict__ out)
{
    __shared__ float xs[Dn];   // GEMM path only (4 KB)

    const int bid = blockIdx.x;
    const int t   = threadIdx.x;

    if (bid < NB_GEMM) {
        // ---- GEMM + tanh + u_new + E_b path (short block, exits early) ----
        const int i     = bid >> 2;          // batch row
        const int hbase = (bid & 3) * 256;   // h chunk

        const float4* xr = reinterpret_cast<const float4*>(x + i * Dn);
        reinterpret_cast<float4*>(xs)[t] = xr[t];
        __syncthreads();

        const int h = hbase + t;
        const float* wc = w + h;
        float acc = 0.0f;
        #pragma unroll 16
        for (int d = 0; d < Dn; ++d) {
            acc = fmaf(xs[d], __ldg(wc + d * Hn), acc);
        }

        const int ih = i * Hn + h;
        const float a = fmaf(BETA, u[ih], acc + b[h]);
        out[ih]            = tanhf(a);
        out[OFF_UNEW + ih] = a;
        out[OFF_EB   + ih] = fmaf(BETA, E_b[ih], 1.0f);
        return;
    }

    // ---- E_w streaming: persistent warps, full-row depth-2 ping-pong ----
    // Pointer-increment addressing keeps index overhead small enough for
    // 3 blocks/SM at <=84 regs.
    const int lane = t & 31;
    const int W    = (bid - NB_GEMM) * 8 + (t >> 5);   // stream warp id
    const int n    = (ROWS - 1 - W) / NWARPS + 1;      // 5 or 6 rows

    const size_t STEP = (size_t)NWARPS * 256;          // float4s per row-step

    const float4* pl = reinterpret_cast<const float4*>(E_w) + (size_t)W * 256 + lane;
    float4*       ps = reinterpret_cast<float4*>(out + OFF_EW) + (size_t)W * 256 + lane;
    const float*  px = x + W;

    float4 A[8], Bv[8];
    float  xA = __ldg(px);
    LOADP(A, pl);

    float xB;
    bool  pa = true;       // pending buffer is A?

    for (int i = 1; i < n; ++i) {
        pl += STEP;
        px += NWARPS;
        if (pa) {
            xB = __ldg(px);
            LOADP(Bv, pl);          // next row's 8 loads in flight...
            STOREP(A, ps, xA);      // ...while draining previous row
        } else {
            xA = __ldg(px);
            LOADP(A, pl);
            STOREP(Bv, ps, xB);
        }
        ps += STEP;
        pa = !pa;
    }
    if (pa) { STOREP(A, ps, xA); } else { STOREP(Bv, ps, xB); }
}

extern "C" void kernel_launch(void* const* d_in, const int* in_sizes, int n_in,
                              void* d_out, int out_size)
{
    const float* x   = (const float*)d_in[0];   // [32,1024]
    const float* w   = (const float*)d_in[1];   // [1024,1024]
    const float* b   = (const float*)d_in[2];   // [1024]
    const float* u   = (const float*)d_in[3];   // [32,1024]
    const float* E_w = (const float*)d_in[4];   // [1,32,1024,1024]
    const float* E_b = (const float*)d_in[5];   // [1,32,1024]
    float* out = (float*)d_out;

    diag_rtrl_kernel<<<NB_GEMM + NB_EW, 256>>>(x, w, b, u, E_w, E_b, out);
}

// round 14
// speedup vs baseline: 1.1424x; 1.1424x over previous
#include <cuda_runtime.h>
#include <cstdint>

// Problem constants
#define Bn 32
#define Dn 1024
#define Hn 1024
#define BETA 0.9f

// Output layout (reference return order):
//   [0, B*H)              out   = tanh(a)
//   [B*H, 2*B*H)          u_new = a
//   [2*B*H, +B*D*H)       E_w_new = 0.9*E_w + x[i,d]  (broadcast over h)
//   [..., +B*H)           E_b_new = 0.9*E_b + 1
// a[i,h] = 0.9*u[i,h] + sum_d x[i,d]*w[d,h] + b[h]

#define NB_GEMM 128          // short GEMM blocks
#define NB_EW   464          // stream blocks; total 592 = 2 full waves @2/SM
#define NWARPS  (NB_EW * 8)  // 3712 stream warps
#define ROWS    (Bn * Dn)    // 32768 rows of H=1024 floats
#define OFF_UNEW (Bn*Hn)
#define OFF_EW   (2*Bn*Hn)
#define OFF_EB   (2*Bn*Hn + Bn*Dn*Hn)

// half-batch ops over float4 lanes k0..k0+3 of a row
#define LOAD4(arr, r, k0)                                               \
    do { const float4* _s = e4 + (size_t)(r) * 256 + lane;              \
         _Pragma("unroll")                                              \
         for (int _k = (k0); _k < (k0) + 4; ++_k)                       \
             arr[_k] = __ldcs(_s + _k * 32);                            \
    } while (0)

#define STORE4(arr, r, xv, k0)                                          \
    do { float4* _o = o4 + (size_t)(r) * 256 + lane;                    \
         _Pragma("unroll")                                              \
         for (int _k = (k0); _k < (k0) + 4; ++_k) {                     \
             float4 _v;                                                 \
             _v.x = fmaf(BETA, arr[_k].x, xv);                          \
             _v.y = fmaf(BETA, arr[_k].y, xv);                          \
             _v.z = fmaf(BETA, arr[_k].z, xv);                          \
             _v.w = fmaf(BETA, arr[_k].w, xv);                          \
             __stcs(_o + _k * 32, _v);                                  \
         }                                                              \
    } while (0)

__global__ void __launch_bounds__(256)
diag_rtrl_kernel(const float* __restrict__ x,
                 const float* __restrict__ w,
                 const float* __restrict__ b,
                 const float* __restrict__ u,
                 const float* __restrict__ E_w,
                 const float* __restrict__ E_b,
                 float* __restrict__ out)
{
    __shared__ float xs[Dn];   // GEMM path only (4 KB)

    const int bid = blockIdx.x;
    const int t   = threadIdx.x;

    if (bid < NB_GEMM) {
        // ---- GEMM + tanh + u_new + E_b path (short block, exits early) ----
        const int i     = bid >> 2;          // batch row
        const int hbase = (bid & 3) * 256;   // h chunk

        const float4* xr = reinterpret_cast<const float4*>(x + i * Dn);
        reinterpret_cast<float4*>(xs)[t] = xr[t];
        __syncthreads();

        const int h = hbase + t;
        const float* wc = w + h;
        float acc = 0.0f;
        #pragma unroll 16
        for (int d = 0; d < Dn; ++d) {
            acc = fmaf(xs[d], __ldg(wc + d * Hn), acc);
        }

        const int ih = i * Hn + h;
        const float a = fmaf(BETA, u[ih], acc + b[h]);
        out[ih]            = tanhf(a);
        out[OFF_UNEW + ih] = a;
        out[OFF_EB   + ih] = fmaf(BETA, E_b[ih], 1.0f);
        return;
    }

    // ---- E_w streaming: depth-2 row ping-pong, half-batch interleaved ----
    // Stores of row i wait on loads issued a full row earlier; loads re-arm
    // mid-store-phase in contiguous batches of 4.
    const int lane = t & 31;
    const int W    = (bid - NB_GEMM) * 8 + (t >> 5);   // stream warp id
    const int n    = (ROWS - 1 - W) / NWARPS + 1;      // 8 or 9 rows

    const float4* e4 = reinterpret_cast<const float4*>(E_w);
    float4*       o4 = reinterpret_cast<float4*>(out + OFF_EW);

    float4 A[8], Bv[8];
    size_t r  = (size_t)W;
    float  xA = __ldg(x + r);
    LOAD4(A, r, 0);
    LOAD4(A, r, 4);

    size_t rp = r;          // row pending in the active buffer
    float  xB;
    bool   pa = true;       // pending buffer is A?

    for (int i = 1; i < n; ++i) {
        const size_t rn = (size_t)W + (size_t)i * NWARPS;
        if (pa) {
            xB = __ldg(x + rn);
            LOAD4(Bv, rn, 0);          // 4 loads in flight...
            STORE4(A, rp, xA, 0);      // ...store first half of prev row
            LOAD4(Bv, rn, 4);          // re-arm reads mid-store-phase
            STORE4(A, rp, xA, 4);
        } else {
            xA = __ldg(x + rn);
            LOAD4(A, rn, 0);
            STORE4(Bv, rp, xB, 0);
            LOAD4(A, rn, 4);
            STORE4(Bv, rp, xB, 4);
        }
        rp = rn;
        pa = !pa;
    }
    if (pa) { STORE4(A, rp, xA, 0); STORE4(A, rp, xA, 4); }
    else    { STORE4(Bv, rp, xB, 0); STORE4(Bv, rp, xB, 4); }
}

extern "C" void kernel_launch(void* const* d_in, const int* in_sizes, int n_in,
                              void* d_out, int out_size)
{
    const float* x   = (const float*)d_in[0];   // [32,1024]
    const float* w   = (const float*)d_in[1];   // [1024,1024]
    const float* b   = (const float*)d_in[2];   // [1024]
    const float* u   = (const float*)d_in[3];   // [32,1024]
    const float* E_w = (const float*)d_in[4];   // [1,32,1024,1024]
    const float* E_b = (const float*)d_in[5];   // [1,32,1024]
    float* out = (float*)d_out;

    diag_rtrl_kernel<<<NB_GEMM + NB_EW, 256>>>(x, w, b, u, E_w, E_b, out);
}